// round 3
// baseline (speedup 1.0000x reference)
#include <cuda_runtime.h>

#define H2    1024
#define SEQN  65536
#define NCHK  32          // o-chunks for K1
#define NB    512         // persistent fused grid (co-resident: 4/SM x 148)

// Scratch (allocation-free rule: device globals)
__device__ float    g_vpart[NCHK][H2];
__device__ float    g_v[H2];
__device__ unsigned g_maxord;
__device__ float    g_psum[NB];
__device__ unsigned g_sync0, g_sync1;

__device__ __forceinline__ unsigned ordf(float f) {
    unsigned u = __float_as_uint(f);
    return (u & 0x80000000u) ? ~u : (u | 0x80000000u);
}
__device__ __forceinline__ float unordf(unsigned u) {
    return __uint_as_float((u & 0x80000000u) ? (u ^ 0x80000000u) : ~u);
}

// Grid-wide barrier: release-fence, arrive, thread0 spins, block rejoins.
__device__ __forceinline__ void gridsync(unsigned* ctr) {
    __syncthreads();
    if (threadIdx.x == 0) {
        __threadfence();
        atomicAdd(ctr, 1u);
        while (*((volatile unsigned*)ctr) < NB) {}
        __threadfence();
    }
    __syncthreads();
}

// K1: partial v[h] over one 32-wide o-chunk. grid (4, 32), 256 thr. 32-deep MLP.
__global__ void k1_v(const float* __restrict__ W, const float* __restrict__ wv) {
    int h  = blockIdx.x * 256 + threadIdx.x;
    int o0 = blockIdx.y * (H2 / NCHK);
    float acc = 0.f;
#pragma unroll
    for (int i = 0; i < H2 / NCHK; i++)
        acc = fmaf(W[(size_t)(o0 + i) * H2 + h], __ldg(&wv[o0 + i]), acc);
    g_vpart[blockIdx.y][h] = acc;
}

// K1b: fold partials into g_v (deterministic) + reset sync state per replay.
__global__ void k1b_fold(void) {
    int h = blockIdx.x * 256 + threadIdx.x;
    float s = 0.f;
#pragma unroll
    for (int c = 0; c < NCHK; c++) s += g_vpart[c][h];
    g_v[h] = s;
    if (h == 0) { g_maxord = 0u; g_sync0 = 0u; g_sync1 = 0u; }
}

// Fused persistent kernel: energies (DRAM-bound GEMV) + softmax, one launch.
// grid NB=512 blocks x 256 threads; block b owns rows [b*128, b*128+128).
__global__ void __launch_bounds__(256, 4) k_fused(const float* __restrict__ outs,
                                                  float* __restrict__ out) {
    __shared__ __align__(16) float sv[H2];     // v vector
    __shared__ __align__(16) float se[128];    // this block's energies
    __shared__ float smax[8];
    __shared__ float ss[NB];

    ((float4*)sv)[threadIdx.x] = ((const float4*)g_v)[threadIdx.x];
    __syncthreads();

    const int warp = threadIdx.x >> 5, lane = threadIdx.x & 31;
    const float4* sv4 = (const float4*)sv;
    float wmax = -3.402823e38f;

    // ---- Phase 1: e[row] = dot(outputs[row], v), 4 rows/warp concurrently ----
#pragma unroll
    for (int it4 = 0; it4 < 4; it4++) {
        const int lrow = it4 * 32 + warp * 4;              // local row 0..127
        const size_t grow = (size_t)blockIdx.x * 128 + lrow;
        const float4* p0 = (const float4*)(outs + (grow + 0) * H2);
        const float4* p1 = (const float4*)(outs + (grow + 1) * H2);
        const float4* p2 = (const float4*)(outs + (grow + 2) * H2);
        const float4* p3 = (const float4*)(outs + (grow + 3) * H2);
        float a0 = 0.f, a1 = 0.f, a2 = 0.f, a3 = 0.f;
#pragma unroll
        for (int it = 0; it < 8; it++) {
            const int j = it * 32 + lane;
            float4 v = sv4[j];
            float4 x0 = p0[j], x1 = p1[j], x2 = p2[j], x3 = p3[j];
            a0 = fmaf(x0.x, v.x, a0); a0 = fmaf(x0.y, v.y, a0);
            a0 = fmaf(x0.z, v.z, a0); a0 = fmaf(x0.w, v.w, a0);
            a1 = fmaf(x1.x, v.x, a1); a1 = fmaf(x1.y, v.y, a1);
            a1 = fmaf(x1.z, v.z, a1); a1 = fmaf(x1.w, v.w, a1);
            a2 = fmaf(x2.x, v.x, a2); a2 = fmaf(x2.y, v.y, a2);
            a2 = fmaf(x2.z, v.z, a2); a2 = fmaf(x2.w, v.w, a2);
            a3 = fmaf(x3.x, v.x, a3); a3 = fmaf(x3.y, v.y, a3);
            a3 = fmaf(x3.z, v.z, a3); a3 = fmaf(x3.w, v.w, a3);
        }
#pragma unroll
        for (int off = 16; off; off >>= 1) {
            a0 += __shfl_xor_sync(0xffffffffu, a0, off);
            a1 += __shfl_xor_sync(0xffffffffu, a1, off);
            a2 += __shfl_xor_sync(0xffffffffu, a2, off);
            a3 += __shfl_xor_sync(0xffffffffu, a3, off);
        }
        if (lane == 0) {
            se[lrow + 0] = a0; se[lrow + 1] = a1;
            se[lrow + 2] = a2; se[lrow + 3] = a3;
        }
        wmax = fmaxf(wmax, fmaxf(fmaxf(a0, a1), fmaxf(a2, a3)));
    }
    if (lane == 0) smax[warp] = wmax;
    __syncthreads();
    if (threadIdx.x == 0) {
        float m = smax[0];
#pragma unroll
        for (int i = 1; i < 8; i++) m = fmaxf(m, smax[i]);
        atomicMax(&g_maxord, ordf(m));   // order-independent -> deterministic
    }
    gridsync(&g_sync0);

    // ---- Phase 2: exp + per-block partial sum (128 elems -> warp 0) ----
    const float m = unordf(g_maxord);
    if (threadIdx.x < 32) {
        float4 e = ((const float4*)se)[threadIdx.x];
        float4 r;
        r.x = __expf(e.x - m); r.y = __expf(e.y - m);
        r.z = __expf(e.z - m); r.w = __expf(e.w - m);
        ((float4*)out)[blockIdx.x * 32 + threadIdx.x] = r;
        float s = (r.x + r.y) + (r.z + r.w);
#pragma unroll
        for (int off = 16; off; off >>= 1) s += __shfl_xor_sync(0xffffffffu, s, off);
        if (threadIdx.x == 0) g_psum[blockIdx.x] = s;
    }
    gridsync(&g_sync1);

    // ---- Phase 3: redundant deterministic reduce of NB partials + normalize ----
    ss[threadIdx.x]       = g_psum[threadIdx.x];
    ss[threadIdx.x + 256] = g_psum[threadIdx.x + 256];
    __syncthreads();
#pragma unroll
    for (int s = 256; s; s >>= 1) {
        if (threadIdx.x < s) ss[threadIdx.x] += ss[threadIdx.x + s];
        __syncthreads();
    }
    const float inv = 1.0f / ss[0];
    if (threadIdx.x < 32) {
        float4 r = ((const float4*)out)[blockIdx.x * 32 + threadIdx.x];
        r.x *= inv; r.y *= inv; r.z *= inv; r.w *= inv;
        ((float4*)out)[blockIdx.x * 32 + threadIdx.x] = r;
    }
}

extern "C" void kernel_launch(void* const* d_in, const int* in_sizes, int n_in,
                              void* d_out, int out_size) {
    const float* outputs = (const float*)d_in[0];   // [SEQ, 2H]
    const float* W       = (const float*)d_in[1];   // [2H, 2H]
    // d_in[2] = b: constant shift, cancels in softmax -> unused
    const float* wv      = (const float*)d_in[3];   // [1, 2H]
    float* out = (float*)d_out;                     // [1,1,SEQ] float32

    k1_v<<<dim3(H2 / 256, NCHK), 256>>>(W, wv);
    k1b_fold<<<H2 / 256, 256>>>();
    k_fused<<<NB, 256>>>(outputs, out);
}

// round 4
// speedup vs baseline: 1.0515x; 1.0515x over previous
#include <cuda_runtime.h>

#define H2    1024
#define SEQN  65536
#define NCHK  128         // o-chunks for K1 (8 rows each)
#define NB34  64          // k34 grid (trivially co-resident)

// Scratch (allocation-free rule: device globals)
__device__ float    g_vpart[NCHK][H2];
__device__ float    g_v[H2];
__device__ float    g_energy[SEQN];
__device__ unsigned g_maxord;
__device__ float    g_psum[NB34];
__device__ unsigned g_sync0;

__device__ __forceinline__ unsigned ordf(float f) {
    unsigned u = __float_as_uint(f);
    return (u & 0x80000000u) ? ~u : (u | 0x80000000u);
}
__device__ __forceinline__ float unordf(unsigned u) {
    return __uint_as_float((u & 0x80000000u) ? (u ^ 0x80000000u) : ~u);
}

__device__ __forceinline__ void gridsync(unsigned* ctr, unsigned nb) {
    __syncthreads();
    if (threadIdx.x == 0) {
        __threadfence();
        atomicAdd(ctr, 1u);
        while (*((volatile unsigned*)ctr) < nb) {}
        __threadfence();
    }
    __syncthreads();
}

// K1: partial v over an 8-row o-chunk. grid NCHK=128, 256 thr.
// Each thread owns one float4 of h (256x4 = all 1024 h) -> coalesced LDG.128.
__global__ void k1_v(const float* __restrict__ W, const float* __restrict__ wv) {
    const int h4 = threadIdx.x;            // float4 index over h
    const int o0 = blockIdx.x * (H2 / NCHK);
    float4 acc = make_float4(0.f, 0.f, 0.f, 0.f);
#pragma unroll
    for (int i = 0; i < H2 / NCHK; i++) {
        const float w = __ldg(&wv[o0 + i]);
        const float4 x = ((const float4*)(W + (size_t)(o0 + i) * H2))[h4];
        acc.x = fmaf(x.x, w, acc.x); acc.y = fmaf(x.y, w, acc.y);
        acc.z = fmaf(x.z, w, acc.z); acc.w = fmaf(x.w, w, acc.w);
    }
    ((float4*)g_vpart[blockIdx.x])[h4] = acc;
}

// K1b: fold NCHK partials into g_v (deterministic fixed order) + reset state.
// grid 4, 256 thr.
__global__ void k1b_fold(void) {
    int h = blockIdx.x * 256 + threadIdx.x;
    float s = 0.f;
#pragma unroll
    for (int c = 0; c < NCHK; c++) s += g_vpart[c][h];
    g_v[h] = s;
    if (h == 0) { g_maxord = 0u; g_sync0 = 0u; }
}

// K2: e[row] = dot(outputs[row], v). grid 2048, 256 thr; 8 warps x 4 rows,
// all 4 rows accumulated concurrently (proven ~6.5 TB/s shape).
__global__ void __launch_bounds__(256) k2_energy(const float* __restrict__ outs) {
    __shared__ __align__(16) float sv[H2];
    ((float4*)sv)[threadIdx.x] = ((const float4*)g_v)[threadIdx.x];
    __syncthreads();

    const int warp = threadIdx.x >> 5, lane = threadIdx.x & 31;
    const float4* sv4 = (const float4*)sv;
    const int base_row = blockIdx.x * 32 + warp * 4;
    const float4* p0 = (const float4*)(outs + (size_t)(base_row + 0) * H2);
    const float4* p1 = (const float4*)(outs + (size_t)(base_row + 1) * H2);
    const float4* p2 = (const float4*)(outs + (size_t)(base_row + 2) * H2);
    const float4* p3 = (const float4*)(outs + (size_t)(base_row + 3) * H2);

    float a0 = 0.f, a1 = 0.f, a2 = 0.f, a3 = 0.f;
#pragma unroll
    for (int it = 0; it < 8; it++) {
        const int j = it * 32 + lane;
        float4 v = sv4[j];
        float4 x0 = p0[j], x1 = p1[j], x2 = p2[j], x3 = p3[j];
        a0 = fmaf(x0.x, v.x, a0); a0 = fmaf(x0.y, v.y, a0);
        a0 = fmaf(x0.z, v.z, a0); a0 = fmaf(x0.w, v.w, a0);
        a1 = fmaf(x1.x, v.x, a1); a1 = fmaf(x1.y, v.y, a1);
        a1 = fmaf(x1.z, v.z, a1); a1 = fmaf(x1.w, v.w, a1);
        a2 = fmaf(x2.x, v.x, a2); a2 = fmaf(x2.y, v.y, a2);
        a2 = fmaf(x2.z, v.z, a2); a2 = fmaf(x2.w, v.w, a2);
        a3 = fmaf(x3.x, v.x, a3); a3 = fmaf(x3.y, v.y, a3);
        a3 = fmaf(x3.z, v.z, a3); a3 = fmaf(x3.w, v.w, a3);
    }
#pragma unroll
    for (int off = 16; off; off >>= 1) {
        a0 += __shfl_xor_sync(0xffffffffu, a0, off);
        a1 += __shfl_xor_sync(0xffffffffu, a1, off);
        a2 += __shfl_xor_sync(0xffffffffu, a2, off);
        a3 += __shfl_xor_sync(0xffffffffu, a3, off);
    }
    if (lane == 0) {
        g_energy[base_row + 0] = a0;
        g_energy[base_row + 1] = a1;
        g_energy[base_row + 2] = a2;
        g_energy[base_row + 3] = a3;
    }
    float wmax = fmaxf(fmaxf(a0, a1), fmaxf(a2, a3));
    __shared__ float smax[8];
    if (lane == 0) smax[warp] = wmax;
    __syncthreads();
    if (threadIdx.x == 0) {
        float m = smax[0];
#pragma unroll
        for (int i = 1; i < 8; i++) m = fmaxf(m, smax[i]);
        atomicMax(&g_maxord, ordf(m));   // max: order-independent -> deterministic
    }
}

// K34: exp + global sum + normalize in one co-resident kernel (one gridsync).
// grid NB34=64 x 256 thr, float4/thread; exp values live in registers across sync.
__global__ void __launch_bounds__(256) k34_softmax(float* __restrict__ out) {
    const int idx = blockIdx.x * 256 + threadIdx.x;   // float4 index
    const float m = unordf(g_maxord);
    float4 e = ((const float4*)g_energy)[idx];
    float4 r;
    r.x = __expf(e.x - m); r.y = __expf(e.y - m);
    r.z = __expf(e.z - m); r.w = __expf(e.w - m);

    __shared__ float ss[256];
    ss[threadIdx.x] = (r.x + r.y) + (r.z + r.w);
    __syncthreads();
#pragma unroll
    for (int s = 128; s; s >>= 1) {
        if (threadIdx.x < s) ss[threadIdx.x] += ss[threadIdx.x + s];
        __syncthreads();
    }
    if (threadIdx.x == 0) g_psum[blockIdx.x] = ss[0];

    gridsync(&g_sync0, NB34);

    // Every block redundantly reduces the 64 partials (deterministic tree).
    __shared__ float sp[NB34];
    if (threadIdx.x < NB34) sp[threadIdx.x] = g_psum[threadIdx.x];
    __syncthreads();
#pragma unroll
    for (int s = NB34 / 2; s; s >>= 1) {
        if (threadIdx.x < s) sp[threadIdx.x] += sp[threadIdx.x + s];
        __syncthreads();
    }
    const float inv = 1.0f / sp[0];
    r.x *= inv; r.y *= inv; r.z *= inv; r.w *= inv;
    ((float4*)out)[idx] = r;
}

extern "C" void kernel_launch(void* const* d_in, const int* in_sizes, int n_in,
                              void* d_out, int out_size) {
    const float* outputs = (const float*)d_in[0];   // [SEQ, 2H]
    const float* W       = (const float*)d_in[1];   // [2H, 2H]
    // d_in[2] = b: constant shift, cancels in softmax -> unused
    const float* wv      = (const float*)d_in[3];   // [1, 2H]
    float* out = (float*)d_out;                     // [1,1,SEQ] float32

    k1_v<<<NCHK, 256>>>(W, wv);
    k1b_fold<<<H2 / 256, 256>>>();
    k2_energy<<<SEQN / 32, 256>>>(outputs);
    k34_softmax<<<NB34, 256>>>(out);
}

// round 5
// speedup vs baseline: 1.0822x; 1.0292x over previous
#include <cuda_runtime.h>

#define H2    1024
#define SEQN  65536
#define NCHK  128              // o-chunks for K1 (8 rows each)
#define K2B   (SEQN / 32)      // 2048 k2 blocks, 32 rows each
#define NB3   64               // normalize grid

// Scratch (allocation-free rule: device globals; zero-initialized)
__device__ float    g_vpart[NCHK][H2];
__device__ float    g_v[H2];
__device__ float    g_m[K2B];          // per-block energy max
__device__ float    g_s[K2B];          // per-block sum of exp(e - m_b)
__device__ unsigned g_sync0;           // k1 internal barrier (reset by k3)

__device__ __forceinline__ void gridsync(unsigned* ctr, unsigned nb) {
    __syncthreads();
    if (threadIdx.x == 0) {
        __threadfence();
        atomicAdd(ctr, 1u);
        while (*((volatile unsigned*)ctr) < nb) {}
        __threadfence();
    }
    __syncthreads();
}

// K1 (fused): v = W^T @ wv. Phase A: per-8-row partials (coalesced float4).
// Internal gridsync (128 blocks, trivially co-resident). Phase B: fold.
__global__ void __launch_bounds__(256) k1_v(const float* __restrict__ W,
                                            const float* __restrict__ wv) {
    const int h4 = threadIdx.x;                 // float4 index over h
    const int o0 = blockIdx.x * (H2 / NCHK);    // 8 o-rows per block
    float4 acc = make_float4(0.f, 0.f, 0.f, 0.f);
#pragma unroll
    for (int i = 0; i < H2 / NCHK; i++) {
        const float w = __ldg(&wv[o0 + i]);
        const float4 x = __ldcs(&((const float4*)(W + (size_t)(o0 + i) * H2))[h4]);
        acc.x = fmaf(x.x, w, acc.x); acc.y = fmaf(x.y, w, acc.y);
        acc.z = fmaf(x.z, w, acc.z); acc.w = fmaf(x.w, w, acc.w);
    }
    ((float4*)g_vpart[blockIdx.x])[h4] = acc;

    gridsync(&g_sync0, NCHK);

    if (blockIdx.x < 4) {                       // fold: 1024 threads cover all h
        const int h = blockIdx.x * 256 + threadIdx.x;
        float s = 0.f;
#pragma unroll
        for (int c = 0; c < NCHK; c++) s += g_vpart[c][h];  // fixed order
        g_v[h] = s;
    }
}

// K2 (flash): e[row]=dot(outputs[row],v); block computes m_b, writes
// exp(e-m_b) to out and (m_b, s_b). grid 2048 x 256; 8 warps x 4 rows.
__global__ void __launch_bounds__(256) k2_energy(const float* __restrict__ outs,
                                                 float* __restrict__ out) {
    __shared__ __align__(16) float sv[H2];
    __shared__ float se[32];      // block's 32 energies
    __shared__ float smax[8];
    __shared__ float sm_b;
    ((float4*)sv)[threadIdx.x] = ((const float4*)g_v)[threadIdx.x];
    __syncthreads();

    const int warp = threadIdx.x >> 5, lane = threadIdx.x & 31;
    const float4* sv4 = (const float4*)sv;
    const int base_row = blockIdx.x * 32 + warp * 4;
    const float4* p0 = (const float4*)(outs + (size_t)(base_row + 0) * H2);
    const float4* p1 = (const float4*)(outs + (size_t)(base_row + 1) * H2);
    const float4* p2 = (const float4*)(outs + (size_t)(base_row + 2) * H2);
    const float4* p3 = (const float4*)(outs + (size_t)(base_row + 3) * H2);

    float a0 = 0.f, a1 = 0.f, a2 = 0.f, a3 = 0.f;
#pragma unroll
    for (int it = 0; it < 8; it++) {
        const int j = it * 32 + lane;
        float4 v = sv4[j];
        float4 x0 = __ldcs(&p0[j]), x1 = __ldcs(&p1[j]);
        float4 x2 = __ldcs(&p2[j]), x3 = __ldcs(&p3[j]);
        a0 = fmaf(x0.x, v.x, a0); a0 = fmaf(x0.y, v.y, a0);
        a0 = fmaf(x0.z, v.z, a0); a0 = fmaf(x0.w, v.w, a0);
        a1 = fmaf(x1.x, v.x, a1); a1 = fmaf(x1.y, v.y, a1);
        a1 = fmaf(x1.z, v.z, a1); a1 = fmaf(x1.w, v.w, a1);
        a2 = fmaf(x2.x, v.x, a2); a2 = fmaf(x2.y, v.y, a2);
        a2 = fmaf(x2.z, v.z, a2); a2 = fmaf(x2.w, v.w, a2);
        a3 = fmaf(x3.x, v.x, a3); a3 = fmaf(x3.y, v.y, a3);
        a3 = fmaf(x3.z, v.z, a3); a3 = fmaf(x3.w, v.w, a3);
    }
#pragma unroll
    for (int off = 16; off; off >>= 1) {
        a0 += __shfl_xor_sync(0xffffffffu, a0, off);
        a1 += __shfl_xor_sync(0xffffffffu, a1, off);
        a2 += __shfl_xor_sync(0xffffffffu, a2, off);
        a3 += __shfl_xor_sync(0xffffffffu, a3, off);
    }
    if (lane == 0) {
        const int lr = warp * 4;
        se[lr + 0] = a0; se[lr + 1] = a1; se[lr + 2] = a2; se[lr + 3] = a3;
        smax[warp] = fmaxf(fmaxf(a0, a1), fmaxf(a2, a3));
    }
    __syncthreads();
    if (threadIdx.x == 0) {
        float m = smax[0];
#pragma unroll
        for (int i = 1; i < 8; i++) m = fmaxf(m, smax[i]);
        sm_b = m;
    }
    __syncthreads();

    // Flash epilogue: warp 0 writes exp(e - m_b) and (m_b, s_b).
    if (threadIdx.x < 32) {
        const float m = sm_b;
        float ex = __expf(se[threadIdx.x] - m);
        out[blockIdx.x * 32 + threadIdx.x] = ex;
        float s = ex;
#pragma unroll
        for (int off = 16; off; off >>= 1) s += __shfl_xor_sync(0xffffffffu, s, off);
        if (threadIdx.x == 0) { g_m[blockIdx.x] = m; g_s[blockIdx.x] = s; }
    }
}

// K3: gmax over 2048 m_b (order-indep), total = sum s_b*exp(m_b-gmax)
// (fixed tree, redundantly per block), then rescale out. grid 64 x 256, float4.
__global__ void __launch_bounds__(256) k3_norm(float* __restrict__ out) {
    __shared__ float sm[256];

    // gmax: 8 serial per thread + 256-tree (max: order-independent)
    float m = -3.402823e38f;
#pragma unroll
    for (int i = 0; i < K2B / 256; i++) m = fmaxf(m, g_m[threadIdx.x + 256 * i]);
    sm[threadIdx.x] = m;
    __syncthreads();
#pragma unroll
    for (int s = 128; s; s >>= 1) {
        if (threadIdx.x < s) sm[threadIdx.x] = fmaxf(sm[threadIdx.x], sm[threadIdx.x + s]);
        __syncthreads();
    }
    const float gmax = sm[0];
    __syncthreads();

    // total: fixed per-thread order + fixed tree -> deterministic
    float t = 0.f;
#pragma unroll
    for (int i = 0; i < K2B / 256; i++) {
        const int b = threadIdx.x + 256 * i;
        t += g_s[b] * __expf(g_m[b] - gmax);
    }
    sm[threadIdx.x] = t;
    __syncthreads();
#pragma unroll
    for (int s = 128; s; s >>= 1) {
        if (threadIdx.x < s) sm[threadIdx.x] += sm[threadIdx.x + s];
        __syncthreads();
    }
    const float inv_total = 1.0f / sm[0];

    if (blockIdx.x == 0 && threadIdx.x == 0) g_sync0 = 0u;  // reset for next replay

    const int f4 = blockIdx.x * 256 + threadIdx.x;   // float4 index
    const int b  = f4 >> 3;                          // 8 float4 per k2 block
    const float scale = __expf(g_m[b] - gmax) * inv_total;
    float4 r = ((const float4*)out)[f4];
    r.x *= scale; r.y *= scale; r.z *= scale; r.w *= scale;
    ((float4*)out)[f4] = r;
}

extern "C" void kernel_launch(void* const* d_in, const int* in_sizes, int n_in,
                              void* d_out, int out_size) {
    const float* outputs = (const float*)d_in[0];   // [SEQ, 2H]
    const float* W       = (const float*)d_in[1];   // [2H, 2H]
    // d_in[2] = b: constant shift, cancels in softmax -> unused
    const float* wv      = (const float*)d_in[3];   // [1, 2H]
    float* out = (float*)d_out;                     // [1,1,SEQ] float32

    k1_v<<<NCHK, 256>>>(W, wv);
    k2_energy<<<K2B, 256>>>(outputs, out);
    k3_norm<<<NB3, 256>>>(out);
}

// round 6
// speedup vs baseline: 1.1188x; 1.0339x over previous
#include <cuda_runtime.h>

#define H2    1024
#define SEQN  65536
#define NOC   64               // o-chunks (16 rows each) for k1a
#define K2B   (SEQN / 32)      // 2048 k2 blocks, 32 rows each
#define NB3   64               // normalize grid

// Scratch (allocation-free rule: device globals)
__device__ float g_vpart[NOC][H2];
__device__ float g_v[H2];
__device__ float g_m[K2B];          // per-block energy max
__device__ float g_s[K2B];          // per-block sum of exp(e - m_b)

// K1a: partial v over one 16-row o-chunk, with in-block fold 4->1.
// grid (4 h-quarters, NOC) = 256 blocks x 256 thr; thread = (osub, hl).
__global__ void __launch_bounds__(256) k1a_v(const float* __restrict__ W,
                                             const float* __restrict__ wv) {
    __shared__ __align__(16) float4 red[256];
    const int osub = threadIdx.x >> 6;          // 0..3
    const int hl   = threadIdx.x & 63;          // local float4 index
    const int h4   = blockIdx.x * 64 + hl;      // global float4 index over h
    const int o0   = blockIdx.y * 16;

    float4 acc = make_float4(0.f, 0.f, 0.f, 0.f);
#pragma unroll
    for (int i = 0; i < 4; i++) {               // 4 independent loads (MLP 4)
        const int row = o0 + osub + i * 4;
        const float w = __ldg(&wv[row]);
        const float4 x = __ldcs(&((const float4*)(W + (size_t)row * H2))[h4]);
        acc.x = fmaf(x.x, w, acc.x); acc.y = fmaf(x.y, w, acc.y);
        acc.z = fmaf(x.z, w, acc.z); acc.w = fmaf(x.w, w, acc.w);
    }
    red[threadIdx.x] = acc;
    __syncthreads();
    if (osub == 0) {                            // fixed-order fold 4 -> 1
        float4 r0 = red[hl],       r1 = red[hl + 64];
        float4 r2 = red[hl + 128], r3 = red[hl + 192];
        float4 s;
        s.x = (r0.x + r1.x) + (r2.x + r3.x);
        s.y = (r0.y + r1.y) + (r2.y + r3.y);
        s.z = (r0.z + r1.z) + (r2.z + r3.z);
        s.w = (r0.w + r1.w) + (r2.w + r3.w);
        ((float4*)g_vpart[blockIdx.y])[h4] = s;
    }
}

// K1b: fold NOC=64 partials into g_v (deterministic fixed order). grid 4 x 256.
__global__ void __launch_bounds__(256) k1b_fold(void) {
    const int h = blockIdx.x * 256 + threadIdx.x;
    float s = 0.f;
#pragma unroll
    for (int c = 0; c < NOC; c++) s += g_vpart[c][h];
    g_v[h] = s;
}

// K2 (flash): e[row]=dot(outputs[row],v); block computes m_b, writes
// exp(e-m_b) to out and (m_b, s_b). grid 2048 x 256; 8 warps x 4 rows.
__global__ void __launch_bounds__(256) k2_energy(const float* __restrict__ outs,
                                                 float* __restrict__ out) {
    __shared__ __align__(16) float sv[H2];
    __shared__ float se[32];
    __shared__ float smax[8];
    __shared__ float sm_b;
    ((float4*)sv)[threadIdx.x] = ((const float4*)g_v)[threadIdx.x];
    __syncthreads();

    const int warp = threadIdx.x >> 5, lane = threadIdx.x & 31;
    const float4* sv4 = (const float4*)sv;
    const int base_row = blockIdx.x * 32 + warp * 4;
    const float4* p0 = (const float4*)(outs + (size_t)(base_row + 0) * H2);
    const float4* p1 = (const float4*)(outs + (size_t)(base_row + 1) * H2);
    const float4* p2 = (const float4*)(outs + (size_t)(base_row + 2) * H2);
    const float4* p3 = (const float4*)(outs + (size_t)(base_row + 3) * H2);

    float a0 = 0.f, a1 = 0.f, a2 = 0.f, a3 = 0.f;
#pragma unroll
    for (int it = 0; it < 8; it++) {
        const int j = it * 32 + lane;
        float4 v = sv4[j];
        float4 x0 = __ldcs(&p0[j]), x1 = __ldcs(&p1[j]);
        float4 x2 = __ldcs(&p2[j]), x3 = __ldcs(&p3[j]);
        a0 = fmaf(x0.x, v.x, a0); a0 = fmaf(x0.y, v.y, a0);
        a0 = fmaf(x0.z, v.z, a0); a0 = fmaf(x0.w, v.w, a0);
        a1 = fmaf(x1.x, v.x, a1); a1 = fmaf(x1.y, v.y, a1);
        a1 = fmaf(x1.z, v.z, a1); a1 = fmaf(x1.w, v.w, a1);
        a2 = fmaf(x2.x, v.x, a2); a2 = fmaf(x2.y, v.y, a2);
        a2 = fmaf(x2.z, v.z, a2); a2 = fmaf(x2.w, v.w, a2);
        a3 = fmaf(x3.x, v.x, a3); a3 = fmaf(x3.y, v.y, a3);
        a3 = fmaf(x3.z, v.z, a3); a3 = fmaf(x3.w, v.w, a3);
    }
#pragma unroll
    for (int off = 16; off; off >>= 1) {
        a0 += __shfl_xor_sync(0xffffffffu, a0, off);
        a1 += __shfl_xor_sync(0xffffffffu, a1, off);
        a2 += __shfl_xor_sync(0xffffffffu, a2, off);
        a3 += __shfl_xor_sync(0xffffffffu, a3, off);
    }
    if (lane == 0) {
        const int lr = warp * 4;
        se[lr + 0] = a0; se[lr + 1] = a1; se[lr + 2] = a2; se[lr + 3] = a3;
        smax[warp] = fmaxf(fmaxf(a0, a1), fmaxf(a2, a3));
    }
    __syncthreads();
    if (threadIdx.x == 0) {
        float m = smax[0];
#pragma unroll
        for (int i = 1; i < 8; i++) m = fmaxf(m, smax[i]);
        sm_b = m;
    }
    __syncthreads();

    if (threadIdx.x < 32) {
        const float m = sm_b;
        float ex = __expf(se[threadIdx.x] - m);
        out[blockIdx.x * 32 + threadIdx.x] = ex;
        float s = ex;
#pragma unroll
        for (int off = 16; off; off >>= 1) s += __shfl_xor_sync(0xffffffffu, s, off);
        if (threadIdx.x == 0) { g_m[blockIdx.x] = m; g_s[blockIdx.x] = s; }
    }
}

// K3: gmax over 2048 m_b (order-indep), total = sum s_b*exp(m_b-gmax)
// (fixed tree, redundant per block), then rescale out. grid 64 x 256, float4.
__global__ void __launch_bounds__(256) k3_norm(float* __restrict__ out) {
    __shared__ float sm[256];

    float m = -3.402823e38f;
#pragma unroll
    for (int i = 0; i < K2B / 256; i++) m = fmaxf(m, g_m[threadIdx.x + 256 * i]);
    sm[threadIdx.x] = m;
    __syncthreads();
#pragma unroll
    for (int s = 128; s; s >>= 1) {
        if (threadIdx.x < s) sm[threadIdx.x] = fmaxf(sm[threadIdx.x], sm[threadIdx.x + s]);
        __syncthreads();
    }
    const float gmax = sm[0];
    __syncthreads();

    float t = 0.f;
#pragma unroll
    for (int i = 0; i < K2B / 256; i++) {
        const int b = threadIdx.x + 256 * i;
        t += g_s[b] * __expf(g_m[b] - gmax);
    }
    sm[threadIdx.x] = t;
    __syncthreads();
#pragma unroll
    for (int s = 128; s; s >>= 1) {
        if (threadIdx.x < s) sm[threadIdx.x] += sm[threadIdx.x + s];
        __syncthreads();
    }
    const float inv_total = 1.0f / sm[0];

    const int f4 = blockIdx.x * 256 + threadIdx.x;   // float4 index
    const int b  = f4 >> 3;                          // 8 float4 per k2 block
    const float scale = __expf(g_m[b] - gmax) * inv_total;
    float4 r = ((const float4*)out)[f4];
    r.x *= scale; r.y *= scale; r.z *= scale; r.w *= scale;
    ((float4*)out)[f4] = r;
}

extern "C" void kernel_launch(void* const* d_in, const int* in_sizes, int n_in,
                              void* d_out, int out_size) {
    const float* outputs = (const float*)d_in[0];   // [SEQ, 2H]
    const float* W       = (const float*)d_in[1];   // [2H, 2H]
    // d_in[2] = b: constant shift, cancels in softmax -> unused
    const float* wv      = (const float*)d_in[3];   // [1, 2H]
    float* out = (float*)d_out;                     // [1,1,SEQ] float32

    k1a_v<<<dim3(4, NOC), 256>>>(W, wv);
    k1b_fold<<<H2 / 256, 256>>>();
    k2_energy<<<K2B, 256>>>(outputs, out);
    k3_norm<<<NB3, 256>>>(out);
}